// round 3
// baseline (speedup 1.0000x reference)
#include <cuda_runtime.h>
#include <math.h>

#define N 512
#define D 512
#define SIGMA 0.5f
#define EPSV 1e-7f

// Scratch (static __device__ — no allocations allowed)
__device__ float g_F[N * N];      // F[i,j] = -sigma*||f_i - f_j||, diag = 0
__device__ float g_rowLoss[N];   // per-row partial of sum(pos_log_probs)
__device__ int   g_ticket;       // last-block ticket (reset by last block)

// ---------------------------------------------------------------------------
// Fixed-order block reduction (deterministic)
// ---------------------------------------------------------------------------
__device__ __forceinline__ float block_reduce_sum(float v, float* sh) {
    int t = threadIdx.x;
    #pragma unroll
    for (int o = 16; o > 0; o >>= 1)
        v += __shfl_down_sync(0xffffffffu, v, o);
    if ((t & 31) == 0) sh[t >> 5] = v;
    __syncthreads();
    if (t < 32) {
        int nw = blockDim.x >> 5;
        v = (t < nw) ? sh[t] : 0.f;
        #pragma unroll
        for (int o = 16; o > 0; o >>= 1)
            v += __shfl_down_sync(0xffffffffu, v, o);
        if (t == 0) sh[0] = v;
    }
    __syncthreads();
    float r = sh[0];
    __syncthreads();
    return r;
}

// ---------------------------------------------------------------------------
// K1: fused norms + Gram -> F.
// 32x32 tile per CTA, 256 threads, 2x2 microtile. Shared tiles stored
// transposed [k][row] (pad 34 floats keeps float2 alignment) so microtile
// fragments load as LDS.64. Row norms are accumulated on the values each
// thread loads (warp w owns columns of rows w+8q) and warp-reduced.
// ---------------------------------------------------------------------------
__global__ void __launch_bounds__(256) gram_kernel(const float* __restrict__ f) {
    __shared__ float As[32][34];   // [k][row]
    __shared__ float Bs[32][34];
    __shared__ float nAs[32];
    __shared__ float nBs[32];

    int bi = blockIdx.y * 32;
    int bj = blockIdx.x * 32;
    int lt = threadIdx.x;
    int tx = lt & 15;
    int ty = lt >> 4;
    int w  = lt >> 5;     // warp id 0..7
    int c  = lt & 31;     // lane = column within k-chunk

    float acc00 = 0.f, acc01 = 0.f, acc10 = 0.f, acc11 = 0.f;
    float na[4] = {0.f, 0.f, 0.f, 0.f};
    float nb[4] = {0.f, 0.f, 0.f, 0.f};

    for (int k0 = 0; k0 < D; k0 += 32) {
        #pragma unroll
        for (int q = 0; q < 4; q++) {
            int r = w + 8 * q;
            float av = f[(size_t)(bi + r) * D + k0 + c];
            float bv = f[(size_t)(bj + r) * D + k0 + c];
            As[c][r] = av;  na[q] += av * av;
            Bs[c][r] = bv;  nb[q] += bv * bv;
        }
        __syncthreads();
        #pragma unroll
        for (int k = 0; k < 32; k++) {
            float2 a = *(const float2*)&As[k][2 * ty];
            float2 b = *(const float2*)&Bs[k][2 * tx];
            acc00 += a.x * b.x;  acc01 += a.x * b.y;
            acc10 += a.y * b.x;  acc11 += a.y * b.y;
        }
        __syncthreads();
    }

    // Warp-reduce the norm partials (lane c holds column c of rows w+8q).
    #pragma unroll
    for (int q = 0; q < 4; q++) {
        float v = na[q], u = nb[q];
        #pragma unroll
        for (int o = 16; o > 0; o >>= 1) {
            v += __shfl_down_sync(0xffffffffu, v, o);
            u += __shfl_down_sync(0xffffffffu, u, o);
        }
        if (c == 0) { nAs[w + 8 * q] = v;  nBs[w + 8 * q] = u; }
    }
    __syncthreads();

    int j0 = bj + 2 * tx;
    float nb0 = nBs[2 * tx], nb1 = nBs[2 * tx + 1];
    {
        int i = bi + 2 * ty;
        float ni = nAs[2 * ty];
        float sq0 = ni + nb0 - 2.f * acc00;
        float sq1 = ni + nb1 - 2.f * acc01;
        float2 o;
        o.x = (i == j0)     ? 0.f : (-SIGMA * sqrtf(fmaxf(sq0, 0.f)));
        o.y = (i == j0 + 1) ? 0.f : (-SIGMA * sqrtf(fmaxf(sq1, 0.f)));
        *(float2*)&g_F[(size_t)i * N + j0] = o;
    }
    {
        int i = bi + 2 * ty + 1;
        float ni = nAs[2 * ty + 1];
        float sq0 = ni + nb0 - 2.f * acc10;
        float sq1 = ni + nb1 - 2.f * acc11;
        float2 o;
        o.x = (i == j0)     ? 0.f : (-SIGMA * sqrtf(fmaxf(sq0, 0.f)));
        o.y = (i == j0 + 1) ? 0.f : (-SIGMA * sqrtf(fmaxf(sq1, 0.f)));
        *(float2*)&g_F[(size_t)i * N + j0] = o;
    }
}

// ---------------------------------------------------------------------------
// K2: per-row softmax + sort-based denom + loss, with fused final reduce.
// One CTA (512 threads) per row i.
//   denom[i,k] = sum_{j != i} S[i,j] * (R[i,j] >= R[i,k])
// computed as: bitonic-sort (R,S) by R asc; suffix-scan S -> T;
// denom[k] = T[lower_bound(R_k)]  (exact, tie-correct: leftmost equal R).
// Last CTA (atomic ticket) does the 512-row final reduction.
// ---------------------------------------------------------------------------
__global__ void __launch_bounds__(512) row_kernel(const float* __restrict__ label,
                                                  float* __restrict__ out) {
    __shared__ __align__(16) float2 rs[N];   // (R, S)
    __shared__ float T[N];                   // suffix sums of S
    __shared__ float red[32];
    __shared__ int sh_last;

    int i = blockIdx.x;
    int t = threadIdx.x;

    float li = label[i];
    float Ft = g_F[(size_t)i * N + t];   // row max is exactly 0 (diagonal)
    float e = expf(Ft);

    float rowsum = block_reduce_sum(e, red);
    float S = (t == i) ? 0.f : e / rowsum;
    float Rt = fabsf(li - label[t]);

    rs[t] = make_float2(Rt, S);
    __syncthreads();

    // Bitonic sort ascending by R (45 compare-exchange steps).
    for (int k = 2; k <= N; k <<= 1) {
        for (int j = k >> 1; j > 0; j >>= 1) {
            int ixj = t ^ j;
            if (ixj > t) {
                float2 a = rs[t], b = rs[ixj];
                bool up = ((t & k) == 0);
                if ((a.x > b.x) == up) { rs[t] = b; rs[ixj] = a; }
            }
            __syncthreads();
        }
    }

    // Suffix (right-to-left inclusive) scan of S: T[p] = sum_{q>=p} S_sorted[q].
    T[t] = rs[t].y;
    __syncthreads();
    for (int d = 1; d < N; d <<= 1) {
        float add = (t + d < N) ? T[t + d] : 0.f;
        __syncthreads();
        T[t] += add;
        __syncthreads();
    }

    // lower_bound(Rt): first p with rs[p].x >= Rt (Rt is present => p < N).
    int lo = 0, hi = N;
    while (lo < hi) {
        int mid = (lo + hi) >> 1;
        if (rs[mid].x < Rt) lo = mid + 1; else hi = mid;
    }
    float denom = T[lo];

    float partial = Ft - ((t == i) ? 0.f : logf(denom + EPSV));
    float rl = block_reduce_sum(partial, red);
    if (t == 0) g_rowLoss[i] = rl;

    // Last-block final reduction (deterministic: fixed-order sum).
    if (t == 0) {
        __threadfence();
        int prev = atomicAdd(&g_ticket, 1);
        sh_last = (prev == N - 1);
    }
    __syncthreads();
    if (sh_last) {
        __threadfence();
        float v = g_rowLoss[t];
        float s = block_reduce_sum(v, red);
        if (t == 0) {
            out[0] = -s / (float)(N * (N - 1));
            g_ticket = 0;   // reset for next graph replay
        }
    }
}

// ---------------------------------------------------------------------------
extern "C" void kernel_launch(void* const* d_in, const int* in_sizes, int n_in,
                              void* d_out, int out_size) {
    const float* feature = (const float*)d_in[0];   // [512, 512] fp32
    const float* label   = (const float*)d_in[1];   // [512, 1]  fp32
    float* out = (float*)d_out;

    gram_kernel<<<dim3(16, 16), 256>>>(feature);
    row_kernel<<<N, 512>>>(label, out);
}

// round 10
// speedup vs baseline: 1.0491x; 1.0491x over previous
#include <cuda_runtime.h>
#include <math.h>

#define N 512
#define D 512
#define SIGMA 0.5f
#define EPSV 1e-7f

// Scratch (static __device__ — no allocations allowed)
__device__ float g_F[N * N];      // F[i,j] = -sigma*||f_i - f_j||, diag = 0
__device__ float g_rowLoss[N];   // per-row partial sums
__device__ int   g_rank[N];      // label-sort rank (stable, tie by index)
__device__ float g_sortedL[N];   // labels in ascending order
__device__ int   g_ticket;       // last-block ticket (reset by last block)

// ---------------------------------------------------------------------------
// Fixed-order block reduction (deterministic)
// ---------------------------------------------------------------------------
__device__ __forceinline__ float block_reduce_sum(float v, float* sh) {
    int t = threadIdx.x;
    #pragma unroll
    for (int o = 16; o > 0; o >>= 1)
        v += __shfl_down_sync(0xffffffffu, v, o);
    if ((t & 31) == 0) sh[t >> 5] = v;
    __syncthreads();
    if (t < 32) {
        int nw = blockDim.x >> 5;
        v = (t < nw) ? sh[t] : 0.f;
        #pragma unroll
        for (int o = 16; o > 0; o >>= 1)
            v += __shfl_down_sync(0xffffffffu, v, o);
        if (t == 0) sh[0] = v;
    }
    __syncthreads();
    float r = sh[0];
    __syncthreads();
    return r;
}

// ---------------------------------------------------------------------------
// K0: global label ranks (stable) + sorted labels. One CTA, O(n^2)/512.
// ---------------------------------------------------------------------------
__global__ void __launch_bounds__(512) rank_kernel(const float* __restrict__ label) {
    __shared__ float L[N];
    int t = threadIdx.x;
    L[t] = label[t];
    __syncthreads();
    float lt = L[t];
    int r = 0;
    #pragma unroll 8
    for (int m = 0; m < N; m++) {
        float lm = L[m];
        r += (lm < lt) || (lm == lt && m < t);
    }
    g_rank[t] = r;
    g_sortedL[r] = lt;
}

// ---------------------------------------------------------------------------
// K1: fused norms + Gram -> F, SYMMETRIC: only tiles with by <= bx computed;
// mirror 2x2 micro-results into the transposed block (F is symmetric).
// 32x32 tile, 256 threads, 2x2 microtile, transposed smem tiles (LDS.64).
// ---------------------------------------------------------------------------
__global__ void __launch_bounds__(256) gram_kernel(const float* __restrict__ f) {
    if (blockIdx.y > blockIdx.x) return;   // lower triangle: mirror-written

    __shared__ float As[32][34];   // [k][row]
    __shared__ float Bs[32][34];
    __shared__ float nAs[32];
    __shared__ float nBs[32];

    int bi = blockIdx.y * 32;
    int bj = blockIdx.x * 32;
    bool diag_tile = (bi == bj);
    int lt = threadIdx.x;
    int tx = lt & 15;
    int ty = lt >> 4;
    int w  = lt >> 5;
    int c  = lt & 31;

    float acc[2][2] = {{0.f, 0.f}, {0.f, 0.f}};
    float na[4] = {0.f, 0.f, 0.f, 0.f};
    float nb[4] = {0.f, 0.f, 0.f, 0.f};

    for (int k0 = 0; k0 < D; k0 += 32) {
        #pragma unroll
        for (int q = 0; q < 4; q++) {
            int r = w + 8 * q;
            float av = f[(size_t)(bi + r) * D + k0 + c];
            float bv = f[(size_t)(bj + r) * D + k0 + c];
            As[c][r] = av;  na[q] += av * av;
            Bs[c][r] = bv;  nb[q] += bv * bv;
        }
        __syncthreads();
        #pragma unroll
        for (int k = 0; k < 32; k++) {
            float2 a = *(const float2*)&As[k][2 * ty];
            float2 b = *(const float2*)&Bs[k][2 * tx];
            acc[0][0] += a.x * b.x;  acc[0][1] += a.x * b.y;
            acc[1][0] += a.y * b.x;  acc[1][1] += a.y * b.y;
        }
        __syncthreads();
    }

    #pragma unroll
    for (int q = 0; q < 4; q++) {
        float v = na[q], u = nb[q];
        #pragma unroll
        for (int o = 16; o > 0; o >>= 1) {
            v += __shfl_down_sync(0xffffffffu, v, o);
            u += __shfl_down_sync(0xffffffffu, u, o);
        }
        if (c == 0) { nAs[w + 8 * q] = v;  nBs[w + 8 * q] = u; }
    }
    __syncthreads();

    int j0 = bj + 2 * tx;
    float nb0 = nBs[2 * tx], nb1 = nBs[2 * tx + 1];
    #pragma unroll
    for (int u = 0; u < 2; u++) {
        int i = bi + 2 * ty + u;
        float ni = nAs[2 * ty + u];
        float sq0 = ni + nb0 - 2.f * acc[u][0];
        float sq1 = ni + nb1 - 2.f * acc[u][1];
        float2 o;
        o.x = (i == j0)     ? 0.f : (-SIGMA * sqrtf(fmaxf(sq0, 0.f)));
        o.y = (i == j0 + 1) ? 0.f : (-SIGMA * sqrtf(fmaxf(sq1, 0.f)));
        *(float2*)&g_F[(size_t)i * N + j0] = o;
        if (!diag_tile) {               // mirror into transposed block
            g_F[(size_t)j0 * N + i]       = o.x;
            g_F[(size_t)(j0 + 1) * N + i] = o.y;
        }
    }
}

// ---------------------------------------------------------------------------
// K2: per-row softmax + interval-sum denom + loss + fused final reduce.
// One CTA (512 threads) per row i.
//   denom[i,k] = sum_{j!=i} S[i,j] * (|l_j - l_i| >= |l_k - l_i|)
//             = totalS - sum over the OPEN ball (l_i - r, l_i + r)
// Ball sum via: scatter S to label-sorted order, inclusive prefix scan I,
// a = upper_bound(l_i - r), b = lower_bound(l_i + r), ball = I[b-1]-I[a-1].
// ---------------------------------------------------------------------------
__global__ void __launch_bounds__(512, 2) row_kernel(const float* __restrict__ label,
                                                     float* __restrict__ out) {
    __shared__ float sS[N];     // S scattered to sorted-label order
    __shared__ float Ls[N];     // sorted labels
    __shared__ float I[N];      // inclusive prefix sums of sS
    __shared__ float red[32];
    __shared__ float wsum[16];
    __shared__ int sh_last;

    int i = blockIdx.x;
    int t = threadIdx.x;
    int lane = t & 31;
    int wid = t >> 5;

    float li = label[i];
    float lt = label[t];
    float Ft = g_F[(size_t)i * N + t];   // row max is exactly 0 (diagonal)
    float e = expf(Ft);

    float rowsum = block_reduce_sum(e, red);
    float S = (t == i) ? 0.f : e / rowsum;

    sS[g_rank[t]] = S;          // stable-rank permutation: no collisions
    Ls[t] = g_sortedL[t];
    __syncthreads();

    // Inclusive block scan of sS -> I (shuffle-based, deterministic order).
    float v = sS[t];
    #pragma unroll
    for (int o = 1; o < 32; o <<= 1) {
        float nvl = __shfl_up_sync(0xffffffffu, v, o);
        if (lane >= o) v += nvl;
    }
    if (lane == 31) wsum[wid] = v;
    __syncthreads();
    if (wid == 0) {
        float wv = (lane < 16) ? wsum[lane] : 0.f;
        #pragma unroll
        for (int o = 1; o < 16; o <<= 1) {
            float nvl = __shfl_up_sync(0xffffffffu, wv, o);
            if (lane >= o) wv += nvl;
        }
        if (lane < 16) wsum[lane] = wv;
    }
    __syncthreads();
    float I_t = v + ((wid > 0) ? wsum[wid - 1] : 0.f);
    I[t] = I_t;
    __syncthreads();

    float r = fabsf(li - lt);
    float xlo = li - r, xhi = li + r;

    // a = upper_bound(xlo): count of labels <= xlo
    int lo = 0, hi = N;
    while (lo < hi) {
        int mid = (lo + hi) >> 1;
        if (Ls[mid] <= xlo) lo = mid + 1; else hi = mid;
    }
    int a = lo;
    // b = lower_bound(xhi): count of labels < xhi
    lo = 0; hi = N;
    while (lo < hi) {
        int mid = (lo + hi) >> 1;
        if (Ls[mid] < xhi) lo = mid + 1; else hi = mid;
    }
    int b = lo;

    float ball = (b > a) ? (I[b - 1] - ((a > 0) ? I[a - 1] : 0.f)) : 0.f;
    float denom = I[N - 1] - ball;

    float partial = Ft - ((t == i) ? 0.f : logf(denom + EPSV));
    float rl = block_reduce_sum(partial, red);
    if (t == 0) g_rowLoss[i] = rl;

    // Last-block final reduction (deterministic fixed-order sum).
    if (t == 0) {
        __threadfence();
        int prev = atomicAdd(&g_ticket, 1);
        sh_last = (prev == N - 1);
    }
    __syncthreads();
    if (sh_last) {
        __threadfence();
        float vv = g_rowLoss[t];
        float s = block_reduce_sum(vv, red);
        if (t == 0) {
            out[0] = -s / (float)(N * (N - 1));
            g_ticket = 0;   // reset for next graph replay
        }
    }
}

// ---------------------------------------------------------------------------
extern "C" void kernel_launch(void* const* d_in, const int* in_sizes, int n_in,
                              void* d_out, int out_size) {
    const float* feature = (const float*)d_in[0];   // [512, 512] fp32
    const float* label   = (const float*)d_in[1];   // [512, 1]  fp32
    float* out = (float*)d_out;

    rank_kernel<<<1, 512>>>(label);
    gram_kernel<<<dim3(16, 16), 256>>>(feature);
    row_kernel<<<N, 512>>>(label, out);
}